// round 13
// baseline (speedup 1.0000x reference)
#include <cuda_runtime.h>
#include <cuda_pipeline_primitives.h>
#include <cstdint>

// GaussianUpsampling — banded softmax attention upsampler, persistent fused kernel.
// hs: (16, 512, 256) f32, ds: (16, 512) f32, masks all-true. out: (16, 4096, 256) f32.
// p_attn[f,t] = softmax_t(-0.1 (f - c_t)^2): narrow Gaussian band, monotone centers.
// Adjacent centers differ by <= 8 frames (ds <= 8), so the value window
// [min(f0, c_last) - 12, fh + 12] always contains each frame's nearest center;
// dropped tokens carry relative weight <= ~e^-13.
// Grid = 16 batches x 27 blocks = 432 = one wave (148 SMs x 3 CTAs). Each block:
// one f64 center scan, then 4-5 tiles (stride-27) of the proven tiled band GEMM.

#define DELTA 0.1f
#define DVAL  12.0f
static const int NB  = 16;
static const int TT  = 512;
static const int AD  = 256;
static const int TF  = 4096;

static const int FRB  = 32;   // frames per tile (== warp width: lane = frame)
static const int TPB  = 128;  // tiles per batch
static const int BPB  = 27;   // blocks per batch (16*27 = 432 = single wave)
static const int WMAX = 48;   // max token window per tile

// ---- f32x2 helpers (sm_10x packed fp32) ----
__device__ __forceinline__ uint64_t fma2(uint64_t a, uint64_t b, uint64_t c) {
    uint64_t d;
    asm("fma.rn.f32x2 %0, %1, %2, %3;" : "=l"(d) : "l"(a), "l"(b), "l"(c));
    return d;
}
__device__ __forceinline__ uint64_t pack2(float x, float y) {
    uint64_t d;
    asm("mov.b64 %0, {%1, %2};" : "=l"(d) : "f"(x), "f"(y));
    return d;
}
__device__ __forceinline__ float2 unpack2(uint64_t v) {
    float2 r;
    asm("mov.b64 {%0, %1}, %2;" : "=f"(r.x), "=f"(r.y) : "l"(v));
    return r;
}

__global__ __launch_bounds__(256, 3)
void upsample_kernel(const float* __restrict__ hs, const float* __restrict__ ds,
                     float* __restrict__ out) {
    __shared__ float  s_c[TT];            // all token centers for this batch (2 KB)
    __shared__ float  s_tile[WMAX * AD];  // hs window (48 KB)
    __shared__ float  s_w[WMAX * FRB];    // unnormalized weights (row = token)
    __shared__ float  s_part[8 * FRB];    // per-warp partial sums
    __shared__ float  s_inv[FRB];         // 1/denominator per frame
    __shared__ double s_wsum[8];          // per-warp scan totals

    int tid  = threadIdx.x;
    int warp = tid >> 5, lane = tid & 31;
    int b    = blockIdx.x / BPB;
    int slot = blockIdx.x - b * BPB;

    // ---- Once per block: centers via f64 block scan (thread owns 2 tokens).
    const float* dsb = ds + b * TT;
    float da = dsb[2 * tid], db_ = dsb[2 * tid + 1];
    double v = (double)da + (double)db_;
#pragma unroll
    for (int off = 1; off < 32; off <<= 1) {
        double n = __shfl_up_sync(0xffffffffu, v, off);
        if (lane >= off) v += n;
    }
    if (lane == 31) s_wsum[warp] = v;
    __syncthreads();
    double base = 0.0;
    for (int i = 0; i < warp; i++) base += s_wsum[i];
    double P = v + base;                  // inclusive cumsum through this pair
    s_c[2 * tid]     = (float)(P - (double)db_ - 0.5 * (double)da);
    s_c[2 * tid + 1] = (float)(P - 0.5 * (double)db_);
    __syncthreads();
    float c_last = s_c[TT - 1];

    for (int tile = slot; tile < TPB; tile += BPB) {
        int f0 = tile * FRB;

        // ---- Window: two binary searches on the value band (warp-uniform).
        int wl, W;
        {
            float lov = fminf((float)f0, c_last) - DVAL;
            float hiv = (float)(f0 + FRB - 1) + DVAL;
            int lo = 0, hi = TT;
            while (lo < hi) { int m = (lo + hi) >> 1; if (s_c[m] < lov) lo = m + 1; else hi = m; }
            wl = lo;                                   // first c >= lov (always <= TT-1)
            lo = 0; hi = TT;
            while (lo < hi) { int m = (lo + hi) >> 1; if (s_c[m] <= hiv) lo = m + 1; else hi = m; }
            int wh = lo - 1;                           // last c <= hiv
            if (wh < wl) wh = wl;
            W = wh - wl + 1;
            if (W > WMAX) {                            // ~impossible; keep middle
                int e = W - WMAX;
                wl += e >> 1;
                W = WMAX;
            }
        }

        // ---- Stage hs window via cp.async (overlaps weight computation).
        {
            const float4* src = (const float4*)(hs + ((size_t)(b * TT + wl)) * AD);
            float4* dst = (float4*)s_tile;
            int n4 = W * (AD / 4);
            for (int i = tid; i < n4; i += 256)
                __pipeline_memcpy_async(&dst[i], &src[i], 16);
            __pipeline_commit();
        }

        // ---- Weights: lane = frame, warps split tokens. Analytic max shift:
        // m = -DELTA * max(0, c_first - f, f - c_last)^2 (exact for out-of-range
        // frames; in-range true max >= -1.6 so shift-by-0 is safe in fp32).
        {
            float f  = (float)(f0 + lane);
            float cf = s_c[wl], cl = s_c[wl + W - 1];
            float d0 = fmaxf(fmaxf(cf - f, f - cl), 0.f);
            float m  = -DELTA * d0 * d0;
            float psum = 0.f;
            for (int t = warp; t < W; t += 8) {
                float dd = f - s_c[wl + t];
                float vv = __expf(-DELTA * dd * dd - m);
                s_w[t * FRB + lane] = vv;
                psum += vv;
            }
            s_part[warp * FRB + lane] = psum;
        }
        __pipeline_wait_prior(0);
        __syncthreads();                  // [B1] s_w/s_part/s_tile ready; prior epilogue done

        // warp 0 folds partials into s_inv, then joins the GEMM; visibility to
        // other warps is fenced by [B2] below (s_inv only read in the epilogue).
        if (warp == 0) {
            float s = 0.f;
#pragma unroll
            for (int w = 0; w < 8; w++) s += s_part[w * FRB + lane];
            s_inv[lane] = 1.f / s;
        }

        // ---- Band GEMM: thread = 2 channels x 16 frames (f32x2 frame pairs).
        int ch = (tid & 127) << 1;        // channel base (0..254)
        int fg = (tid >> 7) << 4;         // frame base (0 or 16)

        uint64_t acc[16];
#pragma unroll
        for (int p = 0; p < 16; p++) acc[p] = 0ull;

        const float* tp = s_tile + ch;
        const float* wb = s_w + fg;
        for (int t = 0; t < W; t++) {
            float2 h2 = *(const float2*)(tp + t * AD);
            const ulonglong2* wq = (const ulonglong2*)(wb + t * FRB);
            ulonglong2 q0 = wq[0], q1 = wq[1], q2 = wq[2], q3 = wq[3];
            uint64_t hd0 = pack2(h2.x, h2.x), hd1 = pack2(h2.y, h2.y);
            acc[0]  = fma2(hd0, q0.x, acc[0]);  acc[1]  = fma2(hd0, q0.y, acc[1]);
            acc[2]  = fma2(hd0, q1.x, acc[2]);  acc[3]  = fma2(hd0, q1.y, acc[3]);
            acc[4]  = fma2(hd0, q2.x, acc[4]);  acc[5]  = fma2(hd0, q2.y, acc[5]);
            acc[6]  = fma2(hd0, q3.x, acc[6]);  acc[7]  = fma2(hd0, q3.y, acc[7]);
            acc[8]  = fma2(hd1, q0.x, acc[8]);  acc[9]  = fma2(hd1, q0.y, acc[9]);
            acc[10] = fma2(hd1, q1.x, acc[10]); acc[11] = fma2(hd1, q1.y, acc[11]);
            acc[12] = fma2(hd1, q2.x, acc[12]); acc[13] = fma2(hd1, q2.y, acc[13]);
            acc[14] = fma2(hd1, q3.x, acc[14]); acc[15] = fma2(hd1, q3.y, acc[15]);
        }
        __syncthreads();                  // [B2] GEMM done; s_inv visible

        // ---- Epilogue: normalize, store STG.64 (lanes contiguous in channel).
        float* ob = out + ((size_t)(b * TF + f0 + fg)) * AD + ch;
#pragma unroll
        for (int p = 0; p < 8; p++) {
            float2 iv = *(const float2*)(s_inv + fg + 2 * p);
            float2 a0 = unpack2(acc[p]);       // ch,   frames 2p / 2p+1
            float2 a1 = unpack2(acc[8 + p]);   // ch+1, frames 2p / 2p+1
            *(float2*)(ob + (size_t)(2 * p) * AD)     = make_float2(a0.x * iv.x, a1.x * iv.x);
            *(float2*)(ob + (size_t)(2 * p + 1) * AD) = make_float2(a0.y * iv.y, a1.y * iv.y);
        }
    }
}

extern "C" void kernel_launch(void* const* d_in, const int* in_sizes, int n_in,
                              void* d_out, int out_size) {
    (void)in_sizes; (void)n_in; (void)out_size;
    const float* hs = (const float*)d_in[0];
    const float* ds = (const float*)d_in[1];
    float* out = (float*)d_out;

    upsample_kernel<<<NB * BPB, 256>>>(hs, ds, out);
}

// round 16
// speedup vs baseline: 1.0743x; 1.0743x over previous
#include <cuda_runtime.h>
#include <cuda_pipeline_primitives.h>
#include <cstdint>

// GaussianUpsampling — banded softmax attention upsampler, f32x2 band-GEMM.
// hs: (16, 512, 256) f32, ds: (16, 512) f32, masks all-true. out: (16, 4096, 256) f32.
// p_attn[f,t] = softmax_t(-0.1 (f - c_t)^2): narrow Gaussian band, monotone centers.
// Tokens with |c - f| > 12 frames have relative weight <= ~e^-14 -> dropped.
// Two kernels chained via Programmatic Dependent Launch: upsample launches while
// setup runs and blocks in cudaGridDependencySynchronize() until its writes land.

#define DELTA 0.1f
#define DVAL  12.0f
static const int NB  = 16;
static const int TT  = 512;
static const int AD  = 256;
static const int TF  = 4096;

static const int FRB  = 32;   // frames per block (== warp width: lane = frame)
static const int TPB  = 128;  // tiles per batch
static const int WMAX = 48;   // max token window per block

__device__ float g_centers[NB * TT];
__device__ int2  g_win[NB * TPB];   // (wl, W) per tile

// ---- f32x2 helpers (sm_10x packed fp32) ----
__device__ __forceinline__ uint64_t fma2(uint64_t a, uint64_t b, uint64_t c) {
    uint64_t d;
    asm("fma.rn.f32x2 %0, %1, %2, %3;" : "=l"(d) : "l"(a), "l"(b), "l"(c));
    return d;
}
__device__ __forceinline__ uint64_t pack2(float x, float y) {
    uint64_t d;
    asm("mov.b64 %0, {%1, %2};" : "=l"(d) : "f"(x), "f"(y));
    return d;
}
__device__ __forceinline__ float2 unpack2(uint64_t v) {
    float2 r;
    asm("mov.b64 {%0, %1}, %2;" : "=f"(r.x), "=f"(r.y) : "l"(v));
    return r;
}

// Per batch: double-precision scan for centers, then per-tile window search.
__global__ void setup_kernel(const float* __restrict__ ds) {
    __shared__ float  sc[TT];
    __shared__ double wsum[16];
#if __CUDA_ARCH__ >= 900
    cudaTriggerProgrammaticLaunchCompletion();  // let upsample grid start spinning up
#endif
    int b = blockIdx.x, t = threadIdx.x;
    int warp = t >> 5, lane = t & 31;
    double v = (double)ds[b * TT + t];
    double orig = v;
#pragma unroll
    for (int off = 1; off < 32; off <<= 1) {
        double n = __shfl_up_sync(0xffffffffu, v, off);
        if (lane >= off) v += n;
    }
    if (lane == 31) wsum[warp] = v;
    __syncthreads();
    double base = 0.0;
    for (int i = 0; i < warp; i++) base += wsum[i];
    float c = (float)(v + base - 0.5 * orig);
    g_centers[b * TT + t] = c;
    sc[t] = c;
    __syncthreads();

    if (t < TPB) {
        int f0 = t * FRB;
        float fl = (float)f0, fh = (float)(f0 + FRB - 1);
        // j0: last token with c <= f0 ; j1: first token with c >= f0+FRB-1
        int lo = 0, hi = TT;
        while (lo < hi) { int m = (lo + hi) >> 1; if (sc[m] <= fl) lo = m + 1; else hi = m; }
        int j0 = lo > 0 ? lo - 1 : 0;
        lo = 0; hi = TT;
        while (lo < hi) { int m = (lo + hi) >> 1; if (sc[m] < fh) lo = m + 1; else hi = m; }
        int j1 = lo < TT ? lo : TT - 1;
        // value-based margin around the covering centers
        float lov = sc[j0] - DVAL, hiv = sc[j1] + DVAL;
        lo = 0; hi = TT;
        while (lo < hi) { int m = (lo + hi) >> 1; if (sc[m] < lov) lo = m + 1; else hi = m; }
        int wl = lo; if (wl > j0) wl = j0;
        lo = 0; hi = TT;
        while (lo < hi) { int m = (lo + hi) >> 1; if (sc[m] <= hiv) lo = m + 1; else hi = m; }
        int wh = lo - 1; if (wh < j1) wh = j1;
        if (wh - wl + 1 > WMAX) {
            // graceful shrink: always keep [j0, j1]
            int ex = wh - wl + 1 - WMAX;
            int sl = j0 - wl; if (sl > (ex + 1) / 2) sl = (ex + 1) / 2;
            wl += sl; ex = (wh - wl + 1) - WMAX;
            if (ex > 0) { int sr = wh - j1; if (sr > ex) sr = ex; wh -= sr; }
            if (wh - wl + 1 > WMAX) wh = wl + WMAX - 1;
        }
        g_win[b * TPB + t] = make_int2(wl, wh - wl + 1);
    }
}

__global__ __launch_bounds__(256, 3)
void upsample_kernel(const float* __restrict__ hs, float* __restrict__ out) {
    __shared__ float s_tile[WMAX * AD];   // hs window
    __shared__ float s_w[WMAX * FRB];     // unnormalized weights (row = token)
    __shared__ float s_c[WMAX];           // window centers
    __shared__ float s_part[8 * FRB];     // per-warp partial sums
    __shared__ float s_inv[FRB];          // 1/denominator per frame

    int tid  = threadIdx.x;
    int b    = blockIdx.x >> 7;           // TPB = 128
    int tile = blockIdx.x & (TPB - 1);
    int f0   = tile * FRB;

#if __CUDA_ARCH__ >= 900
    cudaGridDependencySynchronize();      // wait for setup_kernel's writes
#endif

    int2 win = g_win[blockIdx.x];
    int wl = win.x, W = win.y;

    if (tid < W) s_c[tid] = g_centers[b * TT + wl + tid];

    // Stage hs window via cp.async (overlaps with weight computation).
    {
        const float4* src = (const float4*)(hs + ((size_t)(b * TT + wl)) * AD);
        float4* dst = (float4*)s_tile;
        int n4 = W * (AD / 4);
        for (int i = tid; i < n4; i += 256)
            __pipeline_memcpy_async(&dst[i], &src[i], 16);
        __pipeline_commit();
    }
    __syncthreads();   // s_c visible

    // Weights: lane = frame, warps split tokens. Analytic max shift:
    // m = -DELTA * max(0, c_first - f, f - c_last)^2 (exact for out-of-range
    // frames; in-range true max >= -1.6 so shift-by-0 is safe in fp32).
    int warp = tid >> 5, lane = tid & 31;
    {
        float f  = (float)(f0 + lane);
        float cf = s_c[0], cl = s_c[W - 1];
        float d0 = fmaxf(fmaxf(cf - f, f - cl), 0.f);
        float m  = -DELTA * d0 * d0;
        float psum = 0.f;
        for (int t = warp; t < W; t += 8) {
            float dd = f - s_c[t];
            float v = __expf(-DELTA * dd * dd - m);
            s_w[t * FRB + lane] = v;
            psum += v;
        }
        s_part[warp * FRB + lane] = psum;
    }
    __pipeline_wait_prior(0);
    __syncthreads();
    if (warp == 0) {
        float s = 0.f;
#pragma unroll
        for (int w = 0; w < 8; w++) s += s_part[w * FRB + lane];
        s_inv[lane] = 1.f / s;
    }
    __syncthreads();

    // Band GEMM: thread = 2 channels x 16 frames (frame-pair f32x2 accumulators).
    int chg = tid & 127;
    int ch  = chg << 1;                  // channel base (0..254)
    int fg  = (tid >> 7) << 4;           // frame base (0 or 16)

    uint64_t acc[16];
#pragma unroll
    for (int p = 0; p < 16; p++) acc[p] = 0ull;

    const float* tp = s_tile + ch;
    const float* wb = s_w + fg;
    for (int t = 0; t < W; t++) {
        float2 h2 = *(const float2*)(tp + t * AD);
        const ulonglong2* wq = (const ulonglong2*)(wb + t * FRB);
        ulonglong2 q0 = wq[0], q1 = wq[1], q2 = wq[2], q3 = wq[3];
        uint64_t hd0 = pack2(h2.x, h2.x), hd1 = pack2(h2.y, h2.y);
        acc[0]  = fma2(hd0, q0.x, acc[0]);  acc[1]  = fma2(hd0, q0.y, acc[1]);
        acc[2]  = fma2(hd0, q1.x, acc[2]);  acc[3]  = fma2(hd0, q1.y, acc[3]);
        acc[4]  = fma2(hd0, q2.x, acc[4]);  acc[5]  = fma2(hd0, q2.y, acc[5]);
        acc[6]  = fma2(hd0, q3.x, acc[6]);  acc[7]  = fma2(hd0, q3.y, acc[7]);
        acc[8]  = fma2(hd1, q0.x, acc[8]);  acc[9]  = fma2(hd1, q0.y, acc[9]);
        acc[10] = fma2(hd1, q1.x, acc[10]); acc[11] = fma2(hd1, q1.y, acc[11]);
        acc[12] = fma2(hd1, q2.x, acc[12]); acc[13] = fma2(hd1, q2.y, acc[13]);
        acc[14] = fma2(hd1, q3.x, acc[14]); acc[15] = fma2(hd1, q3.y, acc[15]);
    }

    // Epilogue: normalize, store STG.64 (lanes contiguous in channel).
    float4 iv0 = *(const float4*)(s_inv + fg);
    float4 iv1 = *(const float4*)(s_inv + fg + 4);
    float4 iv2 = *(const float4*)(s_inv + fg + 8);
    float4 iv3 = *(const float4*)(s_inv + fg + 12);
    float inv[16] = { iv0.x, iv0.y, iv0.z, iv0.w, iv1.x, iv1.y, iv1.z, iv1.w,
                      iv2.x, iv2.y, iv2.z, iv2.w, iv3.x, iv3.y, iv3.z, iv3.w };
    float* ob = out + ((size_t)(b * TF + f0 + fg)) * AD + ch;
#pragma unroll
    for (int p = 0; p < 8; p++) {
        float2 a0 = unpack2(acc[p]);       // ch,   frames 2p / 2p+1
        float2 a1 = unpack2(acc[8 + p]);   // ch+1, frames 2p / 2p+1
        float i0 = inv[2 * p], i1 = inv[2 * p + 1];
        *(float2*)(ob + (size_t)(2 * p) * AD)     = make_float2(a0.x * i0, a1.x * i0);
        *(float2*)(ob + (size_t)(2 * p + 1) * AD) = make_float2(a0.y * i1, a1.y * i1);
    }
}

extern "C" void kernel_launch(void* const* d_in, const int* in_sizes, int n_in,
                              void* d_out, int out_size) {
    (void)in_sizes; (void)n_in; (void)out_size;
    const float* hs = (const float*)d_in[0];
    const float* ds = (const float*)d_in[1];
    float* out = (float*)d_out;

    setup_kernel<<<NB, TT>>>(ds);

    // Upsample launched with Programmatic Dependent Launch: it may begin
    // spinning up while setup still runs; cudaGridDependencySynchronize()
    // inside gates the reads of g_centers/g_win.
    cudaLaunchConfig_t cfg = {};
    cfg.gridDim  = dim3(NB * TPB);
    cfg.blockDim = dim3(256);
    cfg.dynamicSmemBytes = 0;
    cfg.stream = 0;
    cudaLaunchAttribute attrs[1];
    attrs[0].id = cudaLaunchAttributeProgrammaticStreamSerialization;
    attrs[0].val.programmaticStreamSerializationAllowed = 1;
    cfg.attrs = attrs;
    cfg.numAttrs = 1;
    cudaError_t err = cudaLaunchKernelEx(&cfg, upsample_kernel, hs, out);
    if (err != cudaSuccess) {
        // Fallback: plain serialized launch (still correct).
        upsample_kernel<<<NB * TPB, 256>>>(hs, out);
    }
}